// round 15
// baseline (speedup 1.0000x reference)
#include <cuda_runtime.h>
#include <cuda_fp16.h>
#include <math.h>
#include <stdint.h>

#define NN 50000
#define EE 800000
#define HH 128
#define LL 4
#define SB 196           // scan blocks = ceil(NN/256)
#define NTILES64 782     // ceil(NN/64)
#define GEMM_GRID 296    // 2 blocks per SM

// ---------------- scratch (static device globals; no allocation) -------------
__device__ float  g_hw[(size_t)NN * HH];      // h @ W result per layer (fp32)
__device__ __half g_ah[(size_t)NN * HH];      // GEMM input A (plain fp16)
__device__ int    g_cnt[NN];                  // degree counts; returns to 0 via fill
__device__ int    g_rowstart[NN + 1];
__device__ float  g_isd[NN];
__device__ float  g_invd[NN];
__device__ __align__(16) int2 g_edge[EE];     // packed CSR: {src, norm-bits}
__device__ int    g_part[256];
__device__ __half g_wh16[(size_t)LL * HH * HH]; // fp16-split W hi, [n][k]
__device__ __half g_wl16[(size_t)LL * HH * HH]; // fp16-split W lo, [n][k]

// ---------------- helpers ------------------------------------------------------
__device__ __forceinline__ void cp_async16(uint32_t dst, const void* src, int srcsize) {
    asm volatile("cp.async.cg.shared.global [%0], [%1], 16, %2;"
                 :: "r"(dst), "l"(src), "r"(srcsize) : "memory");
}
__device__ __forceinline__ void cp_commit() {
    asm volatile("cp.async.commit_group;" ::: "memory");
}
__device__ __forceinline__ void cp_wait1() {
    asm volatile("cp.async.wait_group 1;" ::: "memory");
}
__device__ __forceinline__ void cp_wait0() {
    asm volatile("cp.async.wait_group 0;" ::: "memory");
}

#define LDSM4(r, addr) \
    asm volatile("ldmatrix.sync.aligned.m8n8.x4.shared.b16 {%0,%1,%2,%3}, [%4];" \
        : "=r"((r)[0]), "=r"((r)[1]), "=r"((r)[2]), "=r"((r)[3]) : "r"(addr))

#define MMAF16(d, a, b0, b1) \
    asm volatile("mma.sync.aligned.m16n8k16.row.col.f32.f16.f16.f32 " \
                 "{%0,%1,%2,%3},{%4,%5,%6,%7},{%8,%9},{%0,%1,%2,%3};" \
                 : "+f"(d[0]), "+f"(d[1]), "+f"(d[2]), "+f"(d[3]) \
                 : "r"(a[0]), "r"(a[1]), "r"(a[2]), "r"(a[3]), "r"(b0), "r"(b1))

// ---------------- setup kernels ----------------------------------------------
__global__ void k_splitw(const float* __restrict__ W) {
    int i = blockIdx.x * blockDim.x + threadIdx.x;   // over LL*HH*HH
    int l = i >> 14;
    int k = (i >> 7) & 127;
    int n = i & 127;
    float x = W[i];
    __half h = __float2half_rn(x);
    float lf = x - __half2float(h);
    size_t o = ((size_t)l << 14) + (size_t)n * HH + k;
    g_wh16[o] = h;
    g_wl16[o] = __float2half_rn(lf);
}

__global__ void k_splitx(const float* __restrict__ X) {
    int i = blockIdx.x * blockDim.x + threadIdx.x;   // over NN*HH/4
    float4 v = ((const float4*)X)[i];
    __half2 hA = __floats2half2_rn(v.x, v.y);
    __half2 hB = __floats2half2_rn(v.z, v.w);
    ((__half2*)g_ah)[i * 2]     = hA;
    ((__half2*)g_ah)[i * 2 + 1] = hB;
}

__global__ void k_count(const int* __restrict__ dst) {
    int e = blockIdx.x * blockDim.x + threadIdx.x;
    if (e < EE) atomicAdd(&g_cnt[dst[e]], 1);
}

__global__ void k_blocksum() {
    int i = blockIdx.x * 256 + threadIdx.x;
    int v = (i < NN) ? g_cnt[i] : 0;
    int lane = threadIdx.x & 31, w = threadIdx.x >> 5;
    __shared__ int ws[8];
#pragma unroll
    for (int o = 16; o > 0; o >>= 1) v += __shfl_down_sync(0xffffffffu, v, o);
    if (lane == 0) ws[w] = v;
    __syncthreads();
    if (threadIdx.x == 0) {
        int s = 0;
#pragma unroll
        for (int j = 0; j < 8; j++) s += ws[j];
        g_part[blockIdx.x] = s;
    }
}

__global__ void k_scanpart() {
    int t = threadIdx.x;
    int v = (t < SB) ? g_part[t] : 0;
    int lane = t & 31, w = t >> 5;
    int x = v;
#pragma unroll
    for (int o = 1; o < 32; o <<= 1) {
        int y = __shfl_up_sync(0xffffffffu, x, o);
        if (lane >= o) x += y;
    }
    __shared__ int ws[8];
    if (lane == 31) ws[w] = x;
    __syncthreads();
    if (t == 0) {
        int run = 0;
#pragma unroll
        for (int j = 0; j < 8; j++) { int tmp = ws[j]; ws[j] = run; run += tmp; }
    }
    __syncthreads();
    int incl = x + ws[w];
    if (t < SB) g_part[t] = incl - v;
}

__global__ void k_blockscan() {
    int b = blockIdx.x;
    int i = b * 256 + threadIdx.x;
    int v = (i < NN) ? g_cnt[i] : 0;
    int lane = threadIdx.x & 31, w = threadIdx.x >> 5;
    int x = v;
#pragma unroll
    for (int o = 1; o < 32; o <<= 1) {
        int y = __shfl_up_sync(0xffffffffu, x, o);
        if (lane >= o) x += y;
    }
    __shared__ int ws[8];
    if (lane == 31) ws[w] = x;
    __syncthreads();
    if (threadIdx.x == 0) {
        int run = 0;
#pragma unroll
        for (int j = 0; j < 8; j++) { int tmp = ws[j]; ws[j] = run; run += tmp; }
    }
    __syncthreads();
    int incl = x + ws[w];
    int ex = incl - v;
    int base = g_part[b];
    if (i < NN) {
        g_rowstart[i] = base + ex;
        float deg = (float)v + 1.0f;
        g_isd[i]  = rsqrtf(deg);
        g_invd[i] = 1.0f / deg;
        // g_cnt NOT reset; k_fill's atomicSub returns it to 0
    }
    if (i == NN - 1) g_rowstart[NN] = base + ex + v;
}

__global__ void k_fill(const int* __restrict__ src, const int* __restrict__ dst) {
    int e = blockIdx.x * blockDim.x + threadIdx.x;
    if (e < EE) {
        int s = src[e], d = dst[e];
        int pos = atomicSub(&g_cnt[d], 1) - 1;   // g_cnt returns to 0
        int idx = g_rowstart[d] + pos;
        g_edge[idx] = make_int2(s, __float_as_int(g_isd[s] * g_isd[d]));
    }
}

// ---------------- persistent fp16x2 GEMM, tile 64x128, 2 blocks/SM -----------
// grid=296 persistent, 512 threads (16 warps as 2x8). A via cp.async
// double-buffer (17KB each); W (hi/lo full 128x128) staged once (69.6KB).
// smem = 104448 B -> 2 blocks/SM.
#define AST 136                              // smem stride in halves
#define ATILE_B (64 * AST * 2)               // 17408 bytes per A buffer
#define WTILE_B (128 * AST * 2)              // 34816 bytes per W copy
#define GEMM_SMEM_BYTES (2 * ATILE_B + 2 * WTILE_B)

__global__ void __launch_bounds__(512, 2)
k_gemm_tc(const __half* __restrict__ Ah,
          const __half* __restrict__ Wh, const __half* __restrict__ Wl) {
    extern __shared__ char smch[];
    // layout: Abuf0 | Abuf1 | Wh | Wl
    uint32_t sbase = (uint32_t)__cvta_generic_to_shared(smch);
    __half* sW_h = (__half*)(smch + 2 * (size_t)ATILE_B);
    __half* sW_l = (__half*)(smch + 2 * (size_t)ATILE_B + WTILE_B);
    uint32_t wbase = sbase + 2 * ATILE_B;

    const int tid = threadIdx.x;
    const int lane = tid & 31, warp = tid >> 5;
    const int wm = warp >> 3, wn = warp & 7;   // 2x8 warp grid: 32 rows x 16 cols
    const int bid = blockIdx.x;

    int ntiles = 0;
    while (bid + GEMM_GRID * ntiles < NTILES64) ntiles++;

    // fragment lane addressing
    const int rowA = wm * 32 + (lane & 15);
    const int colA = (lane >> 4) * 8;                    // halves
    const int nB   = wn * 16 + (lane & 7) + ((lane >> 4) << 3);
    const int kB   = ((lane >> 3) & 1) * 8;              // halves
    const uint32_t aoff0 = (uint32_t)((rowA * AST + colA) * 2);
    const uint32_t aoff1 = aoff0 + (uint32_t)(16 * AST * 2);
    const uint32_t boff  = wbase + (uint32_t)((nB * AST + kB) * 2);

    // prologue: cp.async A tile 0, stage W hi/lo
    {
        const int row0 = bid * 64;
#pragma unroll
        for (int j = 0; j < 2; j++) {
            int idx = tid + 512 * j;               // 1024 chunks of 16B
            int r = idx >> 4, c = idx & 15;
            int grow = row0 + r;
            int ok = (grow < NN);
            uint32_t d = sbase + (uint32_t)((r * AST + c * 8) * 2);
            cp_async16(d, Ah + (size_t)(ok ? grow : 0) * HH + c * 8, ok ? 16 : 0);
        }
        cp_commit();
    }
    {
        const uint4* Whv = (const uint4*)Wh;       // [n][k] compact, 16B chunks
        const uint4* Wlv = (const uint4*)Wl;
#pragma unroll
        for (int j = 0; j < 4; j++) {
            int idx = tid + 512 * j;               // 2048 chunks
            int n = idx >> 4, c = idx & 15;
            *(uint4*)((char*)sW_h + n * (AST * 2) + c * 16) = Whv[idx];
            *(uint4*)((char*)sW_l + n * (AST * 2) + c * 16) = Wlv[idx];
        }
    }

    float acc[2][2][4];
#pragma unroll
    for (int mt = 0; mt < 2; mt++)
#pragma unroll
        for (int nt = 0; nt < 2; nt++)
#pragma unroll
            for (int c = 0; c < 4; c++) acc[mt][nt][c] = 0.0f;

    for (int s = 0; s < ntiles; s++) {
        __syncthreads();   // prev compute done; W staged at s=0

        if (s + 1 < ntiles) {
            const int row0 = (bid + GEMM_GRID * (s + 1)) * 64;
            const uint32_t bb = sbase + ((s + 1) & 1) * ATILE_B;
#pragma unroll
            for (int j = 0; j < 2; j++) {
                int idx = tid + 512 * j;
                int r = idx >> 4, c = idx & 15;
                int grow = row0 + r;
                int ok = (grow < NN);
                uint32_t d = bb + (uint32_t)((r * AST + c * 8) * 2);
                cp_async16(d, Ah + (size_t)(ok ? grow : 0) * HH + c * 8, ok ? 16 : 0);
            }
            cp_commit();
            cp_wait1();
        } else {
            cp_wait0();
        }
        __syncthreads();   // tile s visible

        const uint32_t aB = sbase + (s & 1) * ATILE_B;

#pragma unroll
        for (int ks = 0; ks < 8; ks++) {
            const uint32_t kadv = (uint32_t)(ks * 32);   // 16 halves = 32B
            unsigned a0[4], a1[4];
            LDSM4(a0, aB + aoff0 + kadv);
            LDSM4(a1, aB + aoff1 + kadv);
            unsigned bh[4], bl[4];
            LDSM4(bh, boff + kadv);
            LDSM4(bl, boff + WTILE_B + kadv);

            MMAF16(acc[0][0], a0, bl[0], bl[1]);
            MMAF16(acc[0][0], a0, bh[0], bh[1]);
            MMAF16(acc[0][1], a0, bl[2], bl[3]);
            MMAF16(acc[0][1], a0, bh[2], bh[3]);
            MMAF16(acc[1][0], a1, bl[0], bl[1]);
            MMAF16(acc[1][0], a1, bh[0], bh[1]);
            MMAF16(acc[1][1], a1, bl[2], bl[3]);
            MMAF16(acc[1][1], a1, bh[2], bh[3]);
        }

        // store tile s, reset acc
        {
            const int row0 = (bid + GEMM_GRID * s) * 64;
            const int g = lane >> 2, t4 = lane & 3;
#pragma unroll
            for (int mt = 0; mt < 2; mt++) {
#pragma unroll
                for (int nt = 0; nt < 2; nt++) {
                    int row = row0 + wm * 32 + mt * 16 + g;
                    int col = wn * 16 + nt * 8 + t4 * 2;
                    if (row < NN)
                        *(float2*)&g_hw[(size_t)row * HH + col] =
                            make_float2(acc[mt][nt][0], acc[mt][nt][1]);
                    if (row + 8 < NN)
                        *(float2*)&g_hw[(size_t)(row + 8) * HH + col] =
                            make_float2(acc[mt][nt][2], acc[mt][nt][3]);
#pragma unroll
                    for (int c = 0; c < 4; c++) acc[mt][nt][c] = 0.0f;
                }
            }
        }
    }
}

// ---------------- fused aggregate + bias + LayerNorm + GELU (+head) ----------
// one warp per node; packed int2 edges, x4 unroll with 4 accumulator sets.
__global__ void k_agg(const float* __restrict__ cb, const float* __restrict__ lg,
                      const float* __restrict__ lb, float* __restrict__ hout,
                      int do_gelu, const float* __restrict__ head_w,
                      const float* __restrict__ head_b, float* __restrict__ scores) {
    int gwarp = (blockIdx.x * blockDim.x + threadIdx.x) >> 5;
    int lane = threadIdx.x & 31;
    if (gwarp >= NN) return;
    int v = gwarp;
    int c4 = lane * 4;

    int beg = g_rowstart[v];
    int end = g_rowstart[v + 1];

    float4 A0 = make_float4(0.f, 0.f, 0.f, 0.f);
    float4 A1 = make_float4(0.f, 0.f, 0.f, 0.f);
    float4 A2 = make_float4(0.f, 0.f, 0.f, 0.f);
    float4 A3 = make_float4(0.f, 0.f, 0.f, 0.f);
    const float* hwb = g_hw + c4;

    int e = beg;
    if ((e & 1) && e < end) {
        int2 p = g_edge[e];
        float n0 = __int_as_float(p.y);
        float4 r = *(const float4*)(hwb + (size_t)p.x * HH);
        A0.x += r.x * n0; A0.y += r.y * n0; A0.z += r.z * n0; A0.w += r.w * n0;
        e++;
    }
    for (; e + 4 <= end; e += 4) {
        int4 p01 = *(const int4*)&g_edge[e];
        int4 p23 = *(const int4*)&g_edge[e + 2];
        float n0 = __int_as_float(p01.y), n1 = __int_as_float(p01.w);
        float n2 = __int_as_float(p23.y), n3 = __int_as_float(p23.w);
        float4 r0 = *(const float4*)(hwb + (size_t)p01.x * HH);
        float4 r1 = *(const float4*)(hwb + (size_t)p01.z * HH);
        float4 r2 = *(const float4*)(hwb + (size_t)p23.x * HH);
        float4 r3 = *(const float4*)(hwb + (size_t)p23.z * HH);
        A0.x += r0.x * n0; A0.y += r0.y * n0; A0.z += r0.z * n0; A0.w += r0.w * n0;
        A1.x += r1.x * n1; A1.y += r1.y * n1; A1.z += r1.z * n1; A1.w += r1.w * n1;
        A2.x += r2.x * n2; A2.y += r2.y * n2; A2.z += r2.z * n2; A2.w += r2.w * n2;
        A3.x += r3.x * n3; A3.y += r3.y * n3; A3.z += r3.z * n3; A3.w += r3.w * n3;
    }
    for (; e < end; e++) {
        int2 p = g_edge[e];
        float n0 = __int_as_float(p.y);
        float4 r = *(const float4*)(hwb + (size_t)p.x * HH);
        A0.x += r.x * n0; A0.y += r.y * n0; A0.z += r.z * n0; A0.w += r.w * n0;
    }

    float invd = g_invd[v];
    float4 sv = *(const float4*)&g_hw[(size_t)v * HH + c4];
    float4 bb = *(const float4*)&cb[c4];
    float a0 = (A0.x + A1.x) + (A2.x + A3.x) + sv.x * invd + bb.x;
    float a1 = (A0.y + A1.y) + (A2.y + A3.y) + sv.y * invd + bb.y;
    float a2 = (A0.z + A1.z) + (A2.z + A3.z) + sv.z * invd + bb.z;
    float a3 = (A0.w + A1.w) + (A2.w + A3.w) + sv.w * invd + bb.w;

    float sum = a0 + a1 + a2 + a3;
    float sq  = a0 * a0 + a1 * a1 + a2 * a2 + a3 * a3;
#pragma unroll
    for (int off = 16; off > 0; off >>= 1) {
        sum += __shfl_xor_sync(0xffffffffu, sum, off);
        sq  += __shfl_xor_sync(0xffffffffu, sq, off);
    }
    float mu = sum * (1.0f / 128.0f);
    float var = sq * (1.0f / 128.0f) - mu * mu;
    float rstd = rsqrtf(var + 1e-5f);

    float4 gg = *(const float4*)&lg[c4];
    float4 bl = *(const float4*)&lb[c4];
    a0 = (a0 - mu) * rstd * gg.x + bl.x;
    a1 = (a1 - mu) * rstd * gg.y + bl.y;
    a2 = (a2 - mu) * rstd * gg.z + bl.z;
    a3 = (a3 - mu) * rstd * gg.w + bl.w;

    if (do_gelu) {
        const float inv_sqrt2 = 0.7071067811865475f;
        a0 = 0.5f * a0 * (1.0f + erff(a0 * inv_sqrt2));
        a1 = 0.5f * a1 * (1.0f + erff(a1 * inv_sqrt2));
        a2 = 0.5f * a2 * (1.0f + erff(a2 * inv_sqrt2));
        a3 = 0.5f * a3 * (1.0f + erff(a3 * inv_sqrt2));
    }

    if (hout) {
        *(float4*)&hout[(size_t)v * HH + c4] = make_float4(a0, a1, a2, a3);
        float4 w = *(const float4*)&head_w[c4];
        float sc = a0 * w.x + a1 * w.y + a2 * w.z + a3 * w.w;
#pragma unroll
        for (int off = 16; off > 0; off >>= 1)
            sc += __shfl_xor_sync(0xffffffffu, sc, off);
        if (lane == 0) scores[v] = sc + head_b[0];
    } else {
        __half2 hA = __floats2half2_rn(a0, a1);
        __half2 hB = __floats2half2_rn(a2, a3);
        __half2* hp = (__half2*)&g_ah[(size_t)v * HH + c4];
        hp[0] = hA; hp[1] = hB;
    }
}

// ---------------- launch ------------------------------------------------------
extern "C" void kernel_launch(void* const* d_in, const int* in_sizes, int n_in,
                              void* d_out, int out_size) {
    const float* x      = (const float*)d_in[0];
    const int*   ei     = (const int*)  d_in[1];
    const float* conv_w = (const float*)d_in[2];
    const float* conv_b = (const float*)d_in[3];
    const float* ln_g   = (const float*)d_in[4];
    const float* ln_b   = (const float*)d_in[5];
    const float* head_w = (const float*)d_in[6];
    const float* head_b = (const float*)d_in[7];
    float* out = (float*)d_out;            // [0,N) scores, [N, N+N*128) h

    const int* src = ei;
    const int* dst = ei + EE;

    cudaFuncSetAttribute(k_gemm_tc, cudaFuncAttributeMaxDynamicSharedMemorySize,
                         GEMM_SMEM_BYTES);

    void* ah_dev = nullptr;
    cudaGetSymbolAddress(&ah_dev, g_ah);
    void* wh_dev = nullptr; void* wl_dev = nullptr;
    cudaGetSymbolAddress(&wh_dev, g_wh16);
    cudaGetSymbolAddress(&wl_dev, g_wl16);
    const __half* ah = (const __half*)ah_dev;
    const __half* wh = (const __half*)wh_dev;
    const __half* wl = (const __half*)wl_dev;

    k_splitw   <<<(LL * HH * HH) / 256, 256>>> (conv_w);          // 1
    k_splitx   <<<(NN * HH / 4) / 256, 256>>> (x);                // 2
    k_count    <<<(EE + 255) / 256, 256>>> (dst);                 // 3
    k_gemm_tc  <<<GEMM_GRID, 512, GEMM_SMEM_BYTES>>> (ah, wh, wl);// 4 <- profiled (layer 0)
    k_blocksum <<<SB, 256>>> ();                                  // 5
    k_scanpart <<<1, 256>>> ();                                   // 6
    k_blockscan<<<SB, 256>>> ();                                  // 7
    k_fill     <<<(EE + 255) / 256, 256>>> (src, dst);            // 8

    for (int l = 0; l < LL; l++) {
        if (l > 0)
            k_gemm_tc<<<GEMM_GRID, 512, GEMM_SMEM_BYTES>>>(
                ah, wh + (size_t)l * HH * HH, wl + (size_t)l * HH * HH);

        bool last = (l == LL - 1);
        k_agg<<<(NN * 32 + 255) / 256, 256>>>(
            conv_b + (size_t)l * HH, ln_g + (size_t)l * HH, ln_b + (size_t)l * HH,
            last ? (out + NN) : nullptr, last ? 0 : 1,
            head_w, head_b, last ? out : nullptr);
    }
}

// round 16
// speedup vs baseline: 1.0435x; 1.0435x over previous
#include <cuda_runtime.h>
#include <cuda_fp16.h>
#include <math.h>
#include <stdint.h>

#define NN 50000
#define EE 800000
#define HH 128
#define LL 4
#define SB 196           // assign blocks = ceil(NN/256)
#define NTILES 391       // ceil(NN/128)
#define GEMM_GRID 148

// ---------------- scratch (static device globals; no allocation) -------------
__device__ float  g_hw[(size_t)NN * HH];      // h @ W result per layer (fp32)
__device__ __half g_ah[(size_t)NN * HH];      // GEMM input A (plain fp16)
__device__ int    g_cnt[NN];                  // degree counts; returns to 0 via fill
__device__ __align__(8) int2 g_rs[NN];        // per-node {edge begin, degree}
__device__ float  g_isd[NN];
__device__ float  g_invd[NN];
__device__ __align__(16) int2 g_edge[EE];     // packed CSR: {src, norm-bits}
__device__ int    g_total;                    // edge-space allocator
__device__ __half g_wh16[(size_t)LL * HH * HH]; // fp16-split W hi, [n][k]
__device__ __half g_wl16[(size_t)LL * HH * HH]; // fp16-split W lo, [n][k]

// ---------------- helpers ------------------------------------------------------
__device__ __forceinline__ void cp_async16(uint32_t dst, const void* src, int srcsize) {
    asm volatile("cp.async.cg.shared.global [%0], [%1], 16, %2;"
                 :: "r"(dst), "l"(src), "r"(srcsize) : "memory");
}
__device__ __forceinline__ void cp_commit() {
    asm volatile("cp.async.commit_group;" ::: "memory");
}
__device__ __forceinline__ void cp_wait1() {
    asm volatile("cp.async.wait_group 1;" ::: "memory");
}
__device__ __forceinline__ void cp_wait0() {
    asm volatile("cp.async.wait_group 0;" ::: "memory");
}

#define LDSM4(r, addr) \
    asm volatile("ldmatrix.sync.aligned.m8n8.x4.shared.b16 {%0,%1,%2,%3}, [%4];" \
        : "=r"((r)[0]), "=r"((r)[1]), "=r"((r)[2]), "=r"((r)[3]) : "r"(addr))

#define MMAF16(d, a, b0, b1) \
    asm volatile("mma.sync.aligned.m16n8k16.row.col.f32.f16.f16.f32 " \
                 "{%0,%1,%2,%3},{%4,%5,%6,%7},{%8,%9},{%0,%1,%2,%3};" \
                 : "+f"(d[0]), "+f"(d[1]), "+f"(d[2]), "+f"(d[3]) \
                 : "r"(a[0]), "r"(a[1]), "r"(a[2]), "r"(a[3]), "r"(b0), "r"(b1))

// ---------------- setup kernels ----------------------------------------------
__global__ void k_splitw(const float* __restrict__ W) {
    int i = blockIdx.x * blockDim.x + threadIdx.x;   // over LL*HH*HH
    if (i == 0) g_total = 0;                         // reset edge allocator
    int l = i >> 14;
    int k = (i >> 7) & 127;
    int n = i & 127;
    float x = W[i];
    __half h = __float2half_rn(x);
    float lf = x - __half2float(h);
    size_t o = ((size_t)l << 14) + (size_t)n * HH + k;
    g_wh16[o] = h;
    g_wl16[o] = __float2half_rn(lf);
}

__global__ void k_splitx(const float* __restrict__ X) {
    int i = blockIdx.x * blockDim.x + threadIdx.x;   // over NN*HH/4
    float4 v = ((const float4*)X)[i];
    __half2 hA = __floats2half2_rn(v.x, v.y);
    __half2 hB = __floats2half2_rn(v.z, v.w);
    ((__half2*)g_ah)[i * 2]     = hA;
    ((__half2*)g_ah)[i * 2 + 1] = hB;
}

__global__ void k_count(const int* __restrict__ dst) {
    int e = blockIdx.x * blockDim.x + threadIdx.x;
    if (e < EE) atomicAdd(&g_cnt[dst[e]], 1);
}

// one-kernel range assignment: warp scan + one atomicAdd per warp.
// Ranges are contiguous per node but NOT ordered by node id (valid CSR).
__global__ void k_assign() {
    int i = blockIdx.x * 256 + threadIdx.x;
    int lane = threadIdx.x & 31;
    int c = (i < NN) ? g_cnt[i] : 0;
    int x = c;
#pragma unroll
    for (int o = 1; o < 32; o <<= 1) {
        int y = __shfl_up_sync(0xffffffffu, x, o);
        if (lane >= o) x += y;
    }
    int wtotal = __shfl_sync(0xffffffffu, x, 31);
    int base = 0;
    if (lane == 31 && wtotal > 0) base = atomicAdd(&g_total, wtotal);
    base = __shfl_sync(0xffffffffu, base, 31);
    if (i < NN) {
        g_rs[i] = make_int2(base + x - c, c);
        float deg = (float)c + 1.0f;
        g_isd[i]  = rsqrtf(deg);
        g_invd[i] = 1.0f / deg;
        // g_cnt NOT reset; k_fill's atomicSub returns it to 0
    }
}

__global__ void k_fill(const int* __restrict__ src, const int* __restrict__ dst) {
    int e = blockIdx.x * blockDim.x + threadIdx.x;
    if (e < EE) {
        int s = src[e], d = dst[e];
        int pos = atomicSub(&g_cnt[d], 1) - 1;   // g_cnt returns to 0
        int idx = g_rs[d].x + pos;
        g_edge[idx] = make_int2(s, __float_as_int(g_isd[s] * g_isd[d]));
    }
}

// ---------------- persistent fp16x2 GEMM (R14 config: tile 128x128) ----------
// grid=148 persistent, 512 threads (16 warps as 4x4). A via cp.async
// double-buffer; W (hi/lo) staged once. smem = 4*34816 = 139264 B.
#define AST 136                              // smem stride in halves
#define ATILE_B (128 * AST * 2)              // 34816 bytes per tile copy
#define GEMM_SMEM_BYTES (4 * ATILE_B)

__global__ void __launch_bounds__(512, 1)
k_gemm_tc(const __half* __restrict__ Ah,
          const __half* __restrict__ Wh, const __half* __restrict__ Wl) {
    extern __shared__ char smch[];
    // layout: Abuf0 | Abuf1 | Wh | Wl
    uint32_t sbase = (uint32_t)__cvta_generic_to_shared(smch);
    __half* sW_h = (__half*)(smch + 2 * (size_t)ATILE_B);
    __half* sW_l = (__half*)(smch + 3 * (size_t)ATILE_B);
    uint32_t wbase = sbase + 2 * ATILE_B;

    const int tid = threadIdx.x;
    const int lane = tid & 31, warp = tid >> 5;
    const int wm = warp >> 2, wn = warp & 3;
    const int bid = blockIdx.x;

    int ntiles = 0;
    while (bid + GEMM_GRID * ntiles < NTILES) ntiles++;

    const int rowA = wm * 32 + (lane & 15);
    const int colA = (lane >> 4) * 8;
    const int nB   = wn * 32 + (lane & 7) + ((lane >> 4) << 3);
    const int kB   = ((lane >> 3) & 1) * 8;
    const uint32_t aoff0 = (uint32_t)((rowA * AST + colA) * 2);
    const uint32_t aoff1 = aoff0 + (uint32_t)(16 * AST * 2);
    const uint32_t boff0 = wbase + (uint32_t)((nB * AST + kB) * 2);
    const uint32_t boff1 = boff0 + (uint32_t)(16 * AST * 2);

    {
        const int row0 = bid * 128;
#pragma unroll
        for (int j = 0; j < 4; j++) {
            int idx = tid + 512 * j;               // 2048 chunks of 16B
            int r = idx >> 4, c = idx & 15;
            int grow = row0 + r;
            int ok = (grow < NN);
            uint32_t d = sbase + (uint32_t)((r * AST + c * 8) * 2);
            cp_async16(d, Ah + (size_t)(ok ? grow : 0) * HH + c * 8, ok ? 16 : 0);
        }
        cp_commit();
    }
    {
        const uint4* Whv = (const uint4*)Wh;
        const uint4* Wlv = (const uint4*)Wl;
#pragma unroll
        for (int j = 0; j < 4; j++) {
            int idx = tid + 512 * j;
            int n = idx >> 4, c = idx & 15;
            *(uint4*)((char*)sW_h + n * (AST * 2) + c * 16) = Whv[idx];
            *(uint4*)((char*)sW_l + n * (AST * 2) + c * 16) = Wlv[idx];
        }
    }

    float acc[2][4][4];
#pragma unroll
    for (int mt = 0; mt < 2; mt++)
#pragma unroll
        for (int nt = 0; nt < 4; nt++)
#pragma unroll
            for (int c = 0; c < 4; c++) acc[mt][nt][c] = 0.0f;

    for (int s = 0; s < ntiles; s++) {
        __syncthreads();

        if (s + 1 < ntiles) {
            const int row0 = (bid + GEMM_GRID * (s + 1)) * 128;
            const uint32_t bb = sbase + ((s + 1) & 1) * ATILE_B;
#pragma unroll
            for (int j = 0; j < 4; j++) {
                int idx = tid + 512 * j;
                int r = idx >> 4, c = idx & 15;
                int grow = row0 + r;
                int ok = (grow < NN);
                uint32_t d = bb + (uint32_t)((r * AST + c * 8) * 2);
                cp_async16(d, Ah + (size_t)(ok ? grow : 0) * HH + c * 8, ok ? 16 : 0);
            }
            cp_commit();
            cp_wait1();
        } else {
            cp_wait0();
        }
        __syncthreads();

        const uint32_t aB = sbase + (s & 1) * ATILE_B;

#pragma unroll
        for (int ks = 0; ks < 8; ks++) {
            const uint32_t kadv = (uint32_t)(ks * 32);   // 16 halves = 32B
            unsigned a0[4], a1[4];
            LDSM4(a0, aB + aoff0 + kadv);
            LDSM4(a1, aB + aoff1 + kadv);
            unsigned bh0[4], bh1[4], bl0[4], bl1[4];
            LDSM4(bh0, boff0 + kadv);
            LDSM4(bh1, boff1 + kadv);
            LDSM4(bl0, boff0 + ATILE_B + kadv);
            LDSM4(bl1, boff1 + ATILE_B + kadv);

            MMAF16(acc[0][0], a0, bl0[0], bl0[1]);
            MMAF16(acc[0][0], a0, bh0[0], bh0[1]);
            MMAF16(acc[0][1], a0, bl0[2], bl0[3]);
            MMAF16(acc[0][1], a0, bh0[2], bh0[3]);
            MMAF16(acc[0][2], a0, bl1[0], bl1[1]);
            MMAF16(acc[0][2], a0, bh1[0], bh1[1]);
            MMAF16(acc[0][3], a0, bl1[2], bl1[3]);
            MMAF16(acc[0][3], a0, bh1[2], bh1[3]);
            MMAF16(acc[1][0], a1, bl0[0], bl0[1]);
            MMAF16(acc[1][0], a1, bh0[0], bh0[1]);
            MMAF16(acc[1][1], a1, bl0[2], bl0[3]);
            MMAF16(acc[1][1], a1, bh0[2], bh0[3]);
            MMAF16(acc[1][2], a1, bl1[0], bl1[1]);
            MMAF16(acc[1][2], a1, bh1[0], bh1[1]);
            MMAF16(acc[1][3], a1, bl1[2], bl1[3]);
            MMAF16(acc[1][3], a1, bh1[2], bh1[3]);
        }

        {
            const int row0 = (bid + GEMM_GRID * s) * 128;
            const int g = lane >> 2, t4 = lane & 3;
#pragma unroll
            for (int mt = 0; mt < 2; mt++) {
#pragma unroll
                for (int nt = 0; nt < 4; nt++) {
                    int row = row0 + wm * 32 + mt * 16 + g;
                    int col = wn * 32 + nt * 8 + t4 * 2;
                    if (row < NN)
                        *(float2*)&g_hw[(size_t)row * HH + col] =
                            make_float2(acc[mt][nt][0], acc[mt][nt][1]);
                    if (row + 8 < NN)
                        *(float2*)&g_hw[(size_t)(row + 8) * HH + col] =
                            make_float2(acc[mt][nt][2], acc[mt][nt][3]);
#pragma unroll
                    for (int c = 0; c < 4; c++) acc[mt][nt][c] = 0.0f;
                }
            }
        }
    }
}

// ---------------- fused aggregate + bias + LayerNorm + GELU (+head) ----------
// one warp per node; packed int2 edges, x4 unroll with 4 accumulator sets.
__global__ void k_agg(const float* __restrict__ cb, const float* __restrict__ lg,
                      const float* __restrict__ lb, float* __restrict__ hout,
                      int do_gelu, const float* __restrict__ head_w,
                      const float* __restrict__ head_b, float* __restrict__ scores) {
    int gwarp = (blockIdx.x * blockDim.x + threadIdx.x) >> 5;
    int lane = threadIdx.x & 31;
    if (gwarp >= NN) return;
    int v = gwarp;
    int c4 = lane * 4;

    int2 rs = g_rs[v];
    int beg = rs.x;
    int end = rs.x + rs.y;

    float4 A0 = make_float4(0.f, 0.f, 0.f, 0.f);
    float4 A1 = make_float4(0.f, 0.f, 0.f, 0.f);
    float4 A2 = make_float4(0.f, 0.f, 0.f, 0.f);
    float4 A3 = make_float4(0.f, 0.f, 0.f, 0.f);
    const float* hwb = g_hw + c4;

    int e = beg;
    if ((e & 1) && e < end) {
        int2 p = g_edge[e];
        float n0 = __int_as_float(p.y);
        float4 r = *(const float4*)(hwb + (size_t)p.x * HH);
        A0.x += r.x * n0; A0.y += r.y * n0; A0.z += r.z * n0; A0.w += r.w * n0;
        e++;
    }
    for (; e + 4 <= end; e += 4) {
        int4 p01 = *(const int4*)&g_edge[e];
        int4 p23 = *(const int4*)&g_edge[e + 2];
        float n0 = __int_as_float(p01.y), n1 = __int_as_float(p01.w);
        float n2 = __int_as_float(p23.y), n3 = __int_as_float(p23.w);
        float4 r0 = *(const float4*)(hwb + (size_t)p01.x * HH);
        float4 r1 = *(const float4*)(hwb + (size_t)p01.z * HH);
        float4 r2 = *(const float4*)(hwb + (size_t)p23.x * HH);
        float4 r3 = *(const float4*)(hwb + (size_t)p23.z * HH);
        A0.x += r0.x * n0; A0.y += r0.y * n0; A0.z += r0.z * n0; A0.w += r0.w * n0;
        A1.x += r1.x * n1; A1.y += r1.y * n1; A1.z += r1.z * n1; A1.w += r1.w * n1;
        A2.x += r2.x * n2; A2.y += r2.y * n2; A2.z += r2.z * n2; A2.w += r2.w * n2;
        A3.x += r3.x * n3; A3.y += r3.y * n3; A3.z += r3.z * n3; A3.w += r3.w * n3;
    }
    for (; e < end; e++) {
        int2 p = g_edge[e];
        float n0 = __int_as_float(p.y);
        float4 r = *(const float4*)(hwb + (size_t)p.x * HH);
        A0.x += r.x * n0; A0.y += r.y * n0; A0.z += r.z * n0; A0.w += r.w * n0;
    }

    float invd = g_invd[v];
    float4 sv = *(const float4*)&g_hw[(size_t)v * HH + c4];
    float4 bb = *(const float4*)&cb[c4];
    float a0 = (A0.x + A1.x) + (A2.x + A3.x) + sv.x * invd + bb.x;
    float a1 = (A0.y + A1.y) + (A2.y + A3.y) + sv.y * invd + bb.y;
    float a2 = (A0.z + A1.z) + (A2.z + A3.z) + sv.z * invd + bb.z;
    float a3 = (A0.w + A1.w) + (A2.w + A3.w) + sv.w * invd + bb.w;

    float sum = a0 + a1 + a2 + a3;
    float sq  = a0 * a0 + a1 * a1 + a2 * a2 + a3 * a3;
#pragma unroll
    for (int off = 16; off > 0; off >>= 1) {
        sum += __shfl_xor_sync(0xffffffffu, sum, off);
        sq  += __shfl_xor_sync(0xffffffffu, sq, off);
    }
    float mu = sum * (1.0f / 128.0f);
    float var = sq * (1.0f / 128.0f) - mu * mu;
    float rstd = rsqrtf(var + 1e-5f);

    float4 gg = *(const float4*)&lg[c4];
    float4 bl = *(const float4*)&lb[c4];
    a0 = (a0 - mu) * rstd * gg.x + bl.x;
    a1 = (a1 - mu) * rstd * gg.y + bl.y;
    a2 = (a2 - mu) * rstd * gg.z + bl.z;
    a3 = (a3 - mu) * rstd * gg.w + bl.w;

    if (do_gelu) {
        const float inv_sqrt2 = 0.7071067811865475f;
        a0 = 0.5f * a0 * (1.0f + erff(a0 * inv_sqrt2));
        a1 = 0.5f * a1 * (1.0f + erff(a1 * inv_sqrt2));
        a2 = 0.5f * a2 * (1.0f + erff(a2 * inv_sqrt2));
        a3 = 0.5f * a3 * (1.0f + erff(a3 * inv_sqrt2));
    }

    if (hout) {
        *(float4*)&hout[(size_t)v * HH + c4] = make_float4(a0, a1, a2, a3);
        float4 w = *(const float4*)&head_w[c4];
        float sc = a0 * w.x + a1 * w.y + a2 * w.z + a3 * w.w;
#pragma unroll
        for (int off = 16; off > 0; off >>= 1)
            sc += __shfl_xor_sync(0xffffffffu, sc, off);
        if (lane == 0) scores[v] = sc + head_b[0];
    } else {
        __half2 hA = __floats2half2_rn(a0, a1);
        __half2 hB = __floats2half2_rn(a2, a3);
        __half2* hp = (__half2*)&g_ah[(size_t)v * HH + c4];
        hp[0] = hA; hp[1] = hB;
    }
}

// ---------------- launch ------------------------------------------------------
extern "C" void kernel_launch(void* const* d_in, const int* in_sizes, int n_in,
                              void* d_out, int out_size) {
    const float* x      = (const float*)d_in[0];
    const int*   ei     = (const int*)  d_in[1];
    const float* conv_w = (const float*)d_in[2];
    const float* conv_b = (const float*)d_in[3];
    const float* ln_g   = (const float*)d_in[4];
    const float* ln_b   = (const float*)d_in[5];
    const float* head_w = (const float*)d_in[6];
    const float* head_b = (const float*)d_in[7];
    float* out = (float*)d_out;            // [0,N) scores, [N, N+N*128) h

    const int* src = ei;
    const int* dst = ei + EE;

    cudaFuncSetAttribute(k_gemm_tc, cudaFuncAttributeMaxDynamicSharedMemorySize,
                         GEMM_SMEM_BYTES);

    void* ah_dev = nullptr;
    cudaGetSymbolAddress(&ah_dev, g_ah);
    void* wh_dev = nullptr; void* wl_dev = nullptr;
    cudaGetSymbolAddress(&wh_dev, g_wh16);
    cudaGetSymbolAddress(&wl_dev, g_wl16);
    const __half* ah = (const __half*)ah_dev;
    const __half* wh = (const __half*)wh_dev;
    const __half* wl = (const __half*)wl_dev;

    k_splitw   <<<(LL * HH * HH) / 256, 256>>> (conv_w);          // 1 (also resets g_total)
    k_splitx   <<<(NN * HH / 4) / 256, 256>>> (x);                // 2
    k_count    <<<(EE + 255) / 256, 256>>> (dst);                 // 3
    k_gemm_tc  <<<GEMM_GRID, 512, GEMM_SMEM_BYTES>>> (ah, wh, wl);// 4 <- profiled (layer 0)
    k_assign   <<<SB, 256>>> ();                                  // 5
    k_fill     <<<(EE + 255) / 256, 256>>> (src, dst);            // 6

    for (int l = 0; l < LL; l++) {
        if (l > 0)
            k_gemm_tc<<<GEMM_GRID, 512, GEMM_SMEM_BYTES>>>(
                ah, wh + (size_t)l * HH * HH, wl + (size_t)l * HH * HH);

        bool last = (l == LL - 1);
        k_agg<<<(NN * 32 + 255) / 256, 256>>>(
            conv_b + (size_t)l * HH, ln_g + (size_t)l * HH, ln_b + (size_t)l * HH,
            last ? (out + NN) : nullptr, last ? 0 : 1,
            head_w, head_b, last ? out : nullptr);
    }
}

// round 17
// speedup vs baseline: 1.1032x; 1.0572x over previous
#include <cuda_runtime.h>
#include <cuda_fp16.h>
#include <math.h>
#include <stdint.h>

#define NN 50000
#define EE 800000
#define HH 128
#define LL 4
#define SB 196           // assign blocks = ceil(NN/256)
#define NTILES 391       // ceil(NN/128)
#define GEMM_GRID 148

#define WELEMS (LL * HH * HH)       // 65536
#define XQUADS (NN * HH / 4)        // 1600000
#define PREP_TOTAL (WELEMS + XQUADS + EE)

// ---------------- scratch (static device globals; no allocation) -------------
__device__ float  g_hw[(size_t)NN * HH];      // h @ W result per layer (fp32)
__device__ __half g_ah[(size_t)NN * HH];      // GEMM input A (plain fp16)
__device__ int    g_cnt[NN];                  // degree counts; returns to 0 via fill
__device__ __align__(8) int2 g_rs[NN];        // per-node {edge begin, degree}
__device__ float  g_isd[NN];
__device__ float  g_invd[NN];
__device__ __align__(16) int2 g_edge[EE];     // packed CSR: {src, norm-bits}
__device__ int    g_total;                    // edge-space allocator
__device__ __half g_wh16[(size_t)LL * HH * HH]; // fp16-split W hi, [n][k]
__device__ __half g_wl16[(size_t)LL * HH * HH]; // fp16-split W lo, [n][k]

// ---------------- helpers ------------------------------------------------------
__device__ __forceinline__ void cp_async16(uint32_t dst, const void* src, int srcsize) {
    asm volatile("cp.async.cg.shared.global [%0], [%1], 16, %2;"
                 :: "r"(dst), "l"(src), "r"(srcsize) : "memory");
}
__device__ __forceinline__ void cp_commit() {
    asm volatile("cp.async.commit_group;" ::: "memory");
}
__device__ __forceinline__ void cp_wait1() {
    asm volatile("cp.async.wait_group 1;" ::: "memory");
}
__device__ __forceinline__ void cp_wait0() {
    asm volatile("cp.async.wait_group 0;" ::: "memory");
}

#define LDSM4(r, addr) \
    asm volatile("ldmatrix.sync.aligned.m8n8.x4.shared.b16 {%0,%1,%2,%3}, [%4];" \
        : "=r"((r)[0]), "=r"((r)[1]), "=r"((r)[2]), "=r"((r)[3]) : "r"(addr))

#define MMAF16(d, a, b0, b1) \
    asm volatile("mma.sync.aligned.m16n8k16.row.col.f32.f16.f16.f32 " \
                 "{%0,%1,%2,%3},{%4,%5,%6,%7},{%8,%9},{%0,%1,%2,%3};" \
                 : "+f"(d[0]), "+f"(d[1]), "+f"(d[2]), "+f"(d[3]) \
                 : "r"(a[0]), "r"(a[1]), "r"(a[2]), "r"(a[3]), "r"(b0), "r"(b1))

// ---------------- setup: merged W-split / X-convert / degree-count ------------
__global__ void k_prep(const float* __restrict__ W, const float* __restrict__ X,
                       const int* __restrict__ dst) {
    int i = blockIdx.x * blockDim.x + threadIdx.x;
    if (i == 0) g_total = 0;
    if (i < WELEMS) {
        int l = i >> 14;
        int k = (i >> 7) & 127;
        int n = i & 127;
        float x = W[i];
        __half h = __float2half_rn(x);
        float lf = x - __half2float(h);
        size_t o = ((size_t)l << 14) + (size_t)n * HH + k;
        g_wh16[o] = h;
        g_wl16[o] = __float2half_rn(lf);
    } else if (i < WELEMS + XQUADS) {
        int j = i - WELEMS;
        float4 v = ((const float4*)X)[j];
        __half2 hA = __floats2half2_rn(v.x, v.y);
        __half2 hB = __floats2half2_rn(v.z, v.w);
        ((__half2*)g_ah)[j * 2]     = hA;
        ((__half2*)g_ah)[j * 2 + 1] = hB;
    } else if (i < PREP_TOTAL) {
        int e = i - WELEMS - XQUADS;
        atomicAdd(&g_cnt[dst[e]], 1);
    }
}

// one-kernel range assignment: warp scan + one atomicAdd per warp.
__global__ void k_assign() {
    int i = blockIdx.x * 256 + threadIdx.x;
    int lane = threadIdx.x & 31;
    int c = (i < NN) ? g_cnt[i] : 0;
    int x = c;
#pragma unroll
    for (int o = 1; o < 32; o <<= 1) {
        int y = __shfl_up_sync(0xffffffffu, x, o);
        if (lane >= o) x += y;
    }
    int wtotal = __shfl_sync(0xffffffffu, x, 31);
    int base = 0;
    if (lane == 31 && wtotal > 0) base = atomicAdd(&g_total, wtotal);
    base = __shfl_sync(0xffffffffu, base, 31);
    if (i < NN) {
        g_rs[i] = make_int2(base + x - c, c);
        float deg = (float)c + 1.0f;
        g_isd[i]  = rsqrtf(deg);
        g_invd[i] = 1.0f / deg;
        // g_cnt NOT reset; k_fill's atomicSub returns it to 0
    }
}

__global__ void k_fill(const int* __restrict__ src, const int* __restrict__ dst) {
    int e = blockIdx.x * blockDim.x + threadIdx.x;
    if (e < EE) {
        int s = src[e], d = dst[e];
        int pos = atomicSub(&g_cnt[d], 1) - 1;   // g_cnt returns to 0
        int idx = g_rs[d].x + pos;
        g_edge[idx] = make_int2(s, __float_as_int(g_isd[s] * g_isd[d]));
    }
}

// ---------------- persistent fp16x2 GEMM (R14 config: tile 128x128) ----------
#define AST 136                              // smem stride in halves
#define ATILE_B (128 * AST * 2)              // 34816 bytes per tile copy
#define GEMM_SMEM_BYTES (4 * ATILE_B)

__global__ void __launch_bounds__(512, 1)
k_gemm_tc(const __half* __restrict__ Ah,
          const __half* __restrict__ Wh, const __half* __restrict__ Wl) {
    extern __shared__ char smch[];
    uint32_t sbase = (uint32_t)__cvta_generic_to_shared(smch);
    __half* sW_h = (__half*)(smch + 2 * (size_t)ATILE_B);
    __half* sW_l = (__half*)(smch + 3 * (size_t)ATILE_B);
    uint32_t wbase = sbase + 2 * ATILE_B;

    const int tid = threadIdx.x;
    const int lane = tid & 31, warp = tid >> 5;
    const int wm = warp >> 2, wn = warp & 3;
    const int bid = blockIdx.x;

    int ntiles = 0;
    while (bid + GEMM_GRID * ntiles < NTILES) ntiles++;

    const int rowA = wm * 32 + (lane & 15);
    const int colA = (lane >> 4) * 8;
    const int nB   = wn * 32 + (lane & 7) + ((lane >> 4) << 3);
    const int kB   = ((lane >> 3) & 1) * 8;
    const uint32_t aoff0 = (uint32_t)((rowA * AST + colA) * 2);
    const uint32_t aoff1 = aoff0 + (uint32_t)(16 * AST * 2);
    const uint32_t boff0 = wbase + (uint32_t)((nB * AST + kB) * 2);
    const uint32_t boff1 = boff0 + (uint32_t)(16 * AST * 2);

    {
        const int row0 = bid * 128;
#pragma unroll
        for (int j = 0; j < 4; j++) {
            int idx = tid + 512 * j;
            int r = idx >> 4, c = idx & 15;
            int grow = row0 + r;
            int ok = (grow < NN);
            uint32_t d = sbase + (uint32_t)((r * AST + c * 8) * 2);
            cp_async16(d, Ah + (size_t)(ok ? grow : 0) * HH + c * 8, ok ? 16 : 0);
        }
        cp_commit();
    }
    {
        const uint4* Whv = (const uint4*)Wh;
        const uint4* Wlv = (const uint4*)Wl;
#pragma unroll
        for (int j = 0; j < 4; j++) {
            int idx = tid + 512 * j;
            int n = idx >> 4, c = idx & 15;
            *(uint4*)((char*)sW_h + n * (AST * 2) + c * 16) = Whv[idx];
            *(uint4*)((char*)sW_l + n * (AST * 2) + c * 16) = Wlv[idx];
        }
    }

    float acc[2][4][4];
#pragma unroll
    for (int mt = 0; mt < 2; mt++)
#pragma unroll
        for (int nt = 0; nt < 4; nt++)
#pragma unroll
            for (int c = 0; c < 4; c++) acc[mt][nt][c] = 0.0f;

    for (int s = 0; s < ntiles; s++) {
        __syncthreads();

        if (s + 1 < ntiles) {
            const int row0 = (bid + GEMM_GRID * (s + 1)) * 128;
            const uint32_t bb = sbase + ((s + 1) & 1) * ATILE_B;
#pragma unroll
            for (int j = 0; j < 4; j++) {
                int idx = tid + 512 * j;
                int r = idx >> 4, c = idx & 15;
                int grow = row0 + r;
                int ok = (grow < NN);
                uint32_t d = bb + (uint32_t)((r * AST + c * 8) * 2);
                cp_async16(d, Ah + (size_t)(ok ? grow : 0) * HH + c * 8, ok ? 16 : 0);
            }
            cp_commit();
            cp_wait1();
        } else {
            cp_wait0();
        }
        __syncthreads();

        const uint32_t aB = sbase + (s & 1) * ATILE_B;

#pragma unroll
        for (int ks = 0; ks < 8; ks++) {
            const uint32_t kadv = (uint32_t)(ks * 32);
            unsigned a0[4], a1[4];
            LDSM4(a0, aB + aoff0 + kadv);
            LDSM4(a1, aB + aoff1 + kadv);
            unsigned bh0[4], bh1[4], bl0[4], bl1[4];
            LDSM4(bh0, boff0 + kadv);
            LDSM4(bh1, boff1 + kadv);
            LDSM4(bl0, boff0 + ATILE_B + kadv);
            LDSM4(bl1, boff1 + ATILE_B + kadv);

            MMAF16(acc[0][0], a0, bl0[0], bl0[1]);
            MMAF16(acc[0][0], a0, bh0[0], bh0[1]);
            MMAF16(acc[0][1], a0, bl0[2], bl0[3]);
            MMAF16(acc[0][1], a0, bh0[2], bh0[3]);
            MMAF16(acc[0][2], a0, bl1[0], bl1[1]);
            MMAF16(acc[0][2], a0, bh1[0], bh1[1]);
            MMAF16(acc[0][3], a0, bl1[2], bl1[3]);
            MMAF16(acc[0][3], a0, bh1[2], bh1[3]);
            MMAF16(acc[1][0], a1, bl0[0], bl0[1]);
            MMAF16(acc[1][0], a1, bh0[0], bh0[1]);
            MMAF16(acc[1][1], a1, bl0[2], bl0[3]);
            MMAF16(acc[1][1], a1, bh0[2], bh0[3]);
            MMAF16(acc[1][2], a1, bl1[0], bl1[1]);
            MMAF16(acc[1][2], a1, bh1[0], bh1[1]);
            MMAF16(acc[1][3], a1, bl1[2], bl1[3]);
            MMAF16(acc[1][3], a1, bh1[2], bh1[3]);
        }

        {
            const int row0 = (bid + GEMM_GRID * s) * 128;
            const int g = lane >> 2, t4 = lane & 3;
#pragma unroll
            for (int mt = 0; mt < 2; mt++) {
#pragma unroll
                for (int nt = 0; nt < 4; nt++) {
                    int row = row0 + wm * 32 + mt * 16 + g;
                    int col = wn * 32 + nt * 8 + t4 * 2;
                    if (row < NN)
                        *(float2*)&g_hw[(size_t)row * HH + col] =
                            make_float2(acc[mt][nt][0], acc[mt][nt][1]);
                    if (row + 8 < NN)
                        *(float2*)&g_hw[(size_t)(row + 8) * HH + col] =
                            make_float2(acc[mt][nt][2], acc[mt][nt][3]);
#pragma unroll
                    for (int c = 0; c < 4; c++) acc[mt][nt][c] = 0.0f;
                }
            }
        }
    }
}

// ---------------- fused aggregate + bias + LayerNorm + GELU (+head) ----------
// one warp per node; 128-thread blocks; prefetched packed edges, x4 unroll.
__global__ void __launch_bounds__(128)
k_agg(const float* __restrict__ cb, const float* __restrict__ lg,
      const float* __restrict__ lb, float* __restrict__ hout,
      int do_gelu, const float* __restrict__ head_w,
      const float* __restrict__ head_b, float* __restrict__ scores) {
    int gwarp = (blockIdx.x * blockDim.x + threadIdx.x) >> 5;
    int lane = threadIdx.x & 31;
    if (gwarp >= NN) return;
    int v = gwarp;
    int c4 = lane * 4;

    int2 rs = g_rs[v];
    int beg = rs.x;
    int end = rs.x + rs.y;

    float4 A0 = make_float4(0.f, 0.f, 0.f, 0.f);
    float4 A1 = make_float4(0.f, 0.f, 0.f, 0.f);
    float4 A2 = make_float4(0.f, 0.f, 0.f, 0.f);
    float4 A3 = make_float4(0.f, 0.f, 0.f, 0.f);
    const float* hwb = g_hw + c4;

    int e = beg;
    if ((e & 1) && e < end) {
        int2 p = g_edge[e];
        float n0 = __int_as_float(p.y);
        float4 r = *(const float4*)(hwb + (size_t)p.x * HH);
        A0.x += r.x * n0; A0.y += r.y * n0; A0.z += r.z * n0; A0.w += r.w * n0;
        e++;
    }
    int nq = (end - e) >> 2;
    if (nq > 0) {
        // software pipeline: edge records prefetched one iteration ahead
        int4 p01 = *(const int4*)&g_edge[e];
        int4 p23 = *(const int4*)&g_edge[e + 2];
        for (int q = 1; q < nq; q++) {
            int4 n01 = *(const int4*)&g_edge[e + 4 * q];
            int4 n23 = *(const int4*)&g_edge[e + 4 * q + 2];
            float m0 = __int_as_float(p01.y), m1 = __int_as_float(p01.w);
            float m2 = __int_as_float(p23.y), m3 = __int_as_float(p23.w);
            float4 r0 = *(const float4*)(hwb + (size_t)p01.x * HH);
            float4 r1 = *(const float4*)(hwb + (size_t)p01.z * HH);
            float4 r2 = *(const float4*)(hwb + (size_t)p23.x * HH);
            float4 r3 = *(const float4*)(hwb + (size_t)p23.z * HH);
            A0.x += r0.x * m0; A0.y += r0.y * m0; A0.z += r0.z * m0; A0.w += r0.w * m0;
            A1.x += r1.x * m1; A1.y += r1.y * m1; A1.z += r1.z * m1; A1.w += r1.w * m1;
            A2.x += r2.x * m2; A2.y += r2.y * m2; A2.z += r2.z * m2; A2.w += r2.w * m2;
            A3.x += r3.x * m3; A3.y += r3.y * m3; A3.z += r3.z * m3; A3.w += r3.w * m3;
            p01 = n01; p23 = n23;
        }
        {
            float m0 = __int_as_float(p01.y), m1 = __int_as_float(p01.w);
            float m2 = __int_as_float(p23.y), m3 = __int_as_float(p23.w);
            float4 r0 = *(const float4*)(hwb + (size_t)p01.x * HH);
            float4 r1 = *(const float4*)(hwb + (size_t)p01.z * HH);
            float4 r2 = *(const float4*)(hwb + (size_t)p23.x * HH);
            float4 r3 = *(const float4*)(hwb + (size_t)p23.z * HH);
            A0.x += r0.x * m0; A0.y += r0.y * m0; A0.z += r0.z * m0; A0.w += r0.w * m0;
            A1.x += r1.x * m1; A1.y += r1.y * m1; A1.z += r1.z * m1; A1.w += r1.w * m1;
            A2.x += r2.x * m2; A2.y += r2.y * m2; A2.z += r2.z * m2; A2.w += r2.w * m2;
            A3.x += r3.x * m3; A3.y += r3.y * m3; A3.z += r3.z * m3; A3.w += r3.w * m3;
        }
        e += nq * 4;
    }
    for (; e < end; e++) {
        int2 p = g_edge[e];
        float n0 = __int_as_float(p.y);
        float4 r = *(const float4*)(hwb + (size_t)p.x * HH);
        A0.x += r.x * n0; A0.y += r.y * n0; A0.z += r.z * n0; A0.w += r.w * n0;
    }

    float invd = g_invd[v];
    float4 sv = *(const float4*)&g_hw[(size_t)v * HH + c4];
    float4 bb = *(const float4*)&cb[c4];
    float a0 = (A0.x + A1.x) + (A2.x + A3.x) + sv.x * invd + bb.x;
    float a1 = (A0.y + A1.y) + (A2.y + A3.y) + sv.y * invd + bb.y;
    float a2 = (A0.z + A1.z) + (A2.z + A3.z) + sv.z * invd + bb.z;
    float a3 = (A0.w + A1.w) + (A2.w + A3.w) + sv.w * invd + bb.w;

    float sum = a0 + a1 + a2 + a3;
    float sq  = a0 * a0 + a1 * a1 + a2 * a2 + a3 * a3;
#pragma unroll
    for (int off = 16; off > 0; off >>= 1) {
        sum += __shfl_xor_sync(0xffffffffu, sum, off);
        sq  += __shfl_xor_sync(0xffffffffu, sq, off);
    }
    float mu = sum * (1.0f / 128.0f);
    float var = sq * (1.0f / 128.0f) - mu * mu;
    float rstd = rsqrtf(var + 1e-5f);

    float4 gg = *(const float4*)&lg[c4];
    float4 bl = *(const float4*)&lb[c4];
    a0 = (a0 - mu) * rstd * gg.x + bl.x;
    a1 = (a1 - mu) * rstd * gg.y + bl.y;
    a2 = (a2 - mu) * rstd * gg.z + bl.z;
    a3 = (a3 - mu) * rstd * gg.w + bl.w;

    if (do_gelu) {
        const float inv_sqrt2 = 0.7071067811865475f;
        a0 = 0.5f * a0 * (1.0f + erff(a0 * inv_sqrt2));
        a1 = 0.5f * a1 * (1.0f + erff(a1 * inv_sqrt2));
        a2 = 0.5f * a2 * (1.0f + erff(a2 * inv_sqrt2));
        a3 = 0.5f * a3 * (1.0f + erff(a3 * inv_sqrt2));
    }

    if (hout) {
        *(float4*)&hout[(size_t)v * HH + c4] = make_float4(a0, a1, a2, a3);
        float4 w = *(const float4*)&head_w[c4];
        float sc = a0 * w.x + a1 * w.y + a2 * w.z + a3 * w.w;
#pragma unroll
        for (int off = 16; off > 0; off >>= 1)
            sc += __shfl_xor_sync(0xffffffffu, sc, off);
        if (lane == 0) scores[v] = sc + head_b[0];
    } else {
        __half2 hA = __floats2half2_rn(a0, a1);
        __half2 hB = __floats2half2_rn(a2, a3);
        __half2* hp = (__half2*)&g_ah[(size_t)v * HH + c4];
        hp[0] = hA; hp[1] = hB;
    }
}

// ---------------- launch ------------------------------------------------------
extern "C" void kernel_launch(void* const* d_in, const int* in_sizes, int n_in,
                              void* d_out, int out_size) {
    const float* x      = (const float*)d_in[0];
    const int*   ei     = (const int*)  d_in[1];
    const float* conv_w = (const float*)d_in[2];
    const float* conv_b = (const float*)d_in[3];
    const float* ln_g   = (const float*)d_in[4];
    const float* ln_b   = (const float*)d_in[5];
    const float* head_w = (const float*)d_in[6];
    const float* head_b = (const float*)d_in[7];
    float* out = (float*)d_out;            // [0,N) scores, [N, N+N*128) h

    const int* src = ei;
    const int* dst = ei + EE;

    cudaFuncSetAttribute(k_gemm_tc, cudaFuncAttributeMaxDynamicSharedMemorySize,
                         GEMM_SMEM_BYTES);

    void* ah_dev = nullptr;
    cudaGetSymbolAddress(&ah_dev, g_ah);
    void* wh_dev = nullptr; void* wl_dev = nullptr;
    cudaGetSymbolAddress(&wh_dev, g_wh16);
    cudaGetSymbolAddress(&wl_dev, g_wl16);
    const __half* ah = (const __half*)ah_dev;
    const __half* wh = (const __half*)wh_dev;
    const __half* wl = (const __half*)wl_dev;

    k_prep   <<<(PREP_TOTAL + 255) / 256, 256>>> (conv_w, x, dst);   // 1
    k_assign <<<SB, 256>>> ();                                       // 2
    k_fill   <<<(EE + 255) / 256, 256>>> (src, dst);                 // 3
    k_gemm_tc<<<GEMM_GRID, 512, GEMM_SMEM_BYTES>>> (ah, wh, wl);     // 4 <- profiled

    for (int l = 0; l < LL; l++) {
        if (l > 0)
            k_gemm_tc<<<GEMM_GRID, 512, GEMM_SMEM_BYTES>>>(
                ah, wh + (size_t)l * HH * HH, wl + (size_t)l * HH * HH);

        bool last = (l == LL - 1);
        k_agg<<<(NN * 32 + 127) / 128, 128>>>(
            conv_b + (size_t)l * HH, ln_g + (size_t)l * HH, ln_b + (size_t)l * HH,
            last ? (out + NN) : nullptr, last ? 0 : 1,
            head_w, head_b, last ? out : nullptr);
    }
}